// round 1
// baseline (speedup 1.0000x reference)
#include <cuda_runtime.h>
#include <math.h>

#define N_NODES 50000
#define N_EDGES 800000
#define DIN 128

// ---------------- scratch (no cudaMalloc allowed) ----------------
__device__ float g_h0[N_NODES * DIN];       // layer-1 output
__device__ float g_h1[N_NODES * DIN];       // layer-2 output
__device__ float g_xp[N_NODES * DIN];       // relu(h @ Wp + bp)
__device__ float g_pooled[N_NODES * DIN];   // segment max
__device__ int   g_rowptr[N_NODES + 1];
__device__ int   g_cursor[N_NODES];
__device__ int   g_csr[N_EDGES];

// ---------------- CSR build ----------------
__global__ void zero_cursor_kernel() {
    int i = blockIdx.x * blockDim.x + threadIdx.x;
    if (i < N_NODES) g_cursor[i] = 0;
}

__global__ void count_deg_kernel(const int* __restrict__ dst) {
    int e = blockIdx.x * blockDim.x + threadIdx.x;
    if (e < N_EDGES) atomicAdd(&g_cursor[dst[e]], 1);
}

// single-block Hillis-Steele scan over 50000 ints (chunked)
__global__ void scan_kernel() {
    __shared__ int sh[1024];
    __shared__ int carry;
    if (threadIdx.x == 0) carry = 0;
    __syncthreads();
    for (int base = 0; base < N_NODES; base += 1024) {
        int i = base + threadIdx.x;
        int v = (i < N_NODES) ? g_cursor[i] : 0;
        sh[threadIdx.x] = v;
        __syncthreads();
        int acc = v;
        #pragma unroll
        for (int off = 1; off < 1024; off <<= 1) {
            int t = (threadIdx.x >= off) ? sh[threadIdx.x - off] : 0;
            __syncthreads();
            acc += t;
            sh[threadIdx.x] = acc;
            __syncthreads();
        }
        int excl = acc - v + carry;
        if (i < N_NODES) { g_rowptr[i] = excl; g_cursor[i] = excl; }
        __syncthreads();
        if (threadIdx.x == 1023) carry = carry + sh[1023];
        __syncthreads();
    }
    if (threadIdx.x == 0) g_rowptr[N_NODES] = carry;
}

__global__ void scatter_kernel(const int* __restrict__ src, const int* __restrict__ dst) {
    int e = blockIdx.x * blockDim.x + threadIdx.x;
    if (e < N_EDGES) {
        int d = dst[e];
        int pos = atomicAdd(&g_cursor[d], 1);
        g_csr[pos] = src[e];
    }
}

// ---------------- pooling: per-node warp max over CSR neighbors ----------------
// relu output >= 0, so init 0 == segment_max (and gives 0 for deg==0, matching ref)
__global__ void pool_kernel() {
    int gwarp = (blockIdx.x * blockDim.x + threadIdx.x) >> 5;
    int lane  = threadIdx.x & 31;
    if (gwarp >= N_NODES) return;
    int s = g_rowptr[gwarp];
    int e = g_rowptr[gwarp + 1];
    float4 m = make_float4(0.f, 0.f, 0.f, 0.f);
    for (int j = s; j < e; j++) {
        int src = g_csr[j];  // broadcast load
        float4 v = *reinterpret_cast<const float4*>(g_xp + (size_t)src * DIN + lane * 4);
        m.x = fmaxf(m.x, v.x); m.y = fmaxf(m.y, v.y);
        m.z = fmaxf(m.z, v.z); m.w = fmaxf(m.w, v.w);
    }
    *reinterpret_cast<float4*>(g_pooled + (size_t)gwarp * DIN + lane * 4) = m;
}

// ---------------- GEMM: BM=64 x BN=DOUT, BK=16, 256 threads, 8xTN per thread ----
// DUAL:  C = A1 @ B1 + A2 @ B2   (K = 256, halves never straddle a BK tile)
// !DUAL: C = A1 @ B1             (K = 128)
// NORM:  +bias, L2-normalize each row (warp shfl reduce), relu
// !NORM: +bias, relu
template <int DOUT, int TN, bool DUAL, bool NORM>
__global__ void __launch_bounds__(256)
gemm_kernel(const float* __restrict__ A1, const float* __restrict__ A2,
            const float* __restrict__ B1, const float* __restrict__ B2,
            const float* __restrict__ bias, float* __restrict__ out)
{
    constexpr int BM = 64, BK = 16;
    constexpr int KT = DUAL ? 16 : 8;
    __shared__ float As[BK][68];   // transposed A tile, stride 68 keeps 16B row align
    __shared__ float Bs[BK][DOUT];

    int tid = threadIdx.x;
    int tx = tid & 31;   // lane == column group owner
    int ty = tid >> 5;   // row group (8 rows each)
    int blockRow = blockIdx.x * BM;

    float acc[8][TN];
    #pragma unroll
    for (int i = 0; i < 8; i++)
        #pragma unroll
        for (int j = 0; j < TN; j++) acc[i][j] = 0.f;

    int arow = tid >> 2;        // 0..63
    int acg  = tid & 3;         // 0..3 (float4 col group)
    int garow = blockRow + arow;
    if (garow >= N_NODES) garow = 0;   // clamp; stores are guarded

    for (int kt = 0; kt < KT; kt++) {
        const float* A = (!DUAL || kt < 8) ? A1 : A2;
        const float* B = (!DUAL || kt < 8) ? B1 : B2;
        int kbase = (kt & 7) * BK;

        // A tile load (64x16), transpose into As
        float4 av = *reinterpret_cast<const float4*>(A + (size_t)garow * DIN + kbase + acg * 4);
        As[acg * 4 + 0][arow] = av.x;
        As[acg * 4 + 1][arow] = av.y;
        As[acg * 4 + 2][arow] = av.z;
        As[acg * 4 + 3][arow] = av.w;

        // B tile load (16 x DOUT)
        constexpr int BF4 = BK * DOUT / 4 / 256;   // 2 for DOUT=128, 1 for DOUT=64
        #pragma unroll
        for (int i = 0; i < BF4; i++) {
            int f = tid + i * 256;
            int brow = f / (DOUT / 4);
            int bc4  = f % (DOUT / 4);
            float4 bv = *reinterpret_cast<const float4*>(B + (size_t)(kbase + brow) * DOUT + bc4 * 4);
            *reinterpret_cast<float4*>(&Bs[brow][bc4 * 4]) = bv;
        }
        __syncthreads();

        #pragma unroll
        for (int k = 0; k < BK; k++) {
            float ra[8];
            const float4* pA = reinterpret_cast<const float4*>(&As[k][ty * 8]);
            float4 a0 = pA[0], a1 = pA[1];
            ra[0]=a0.x; ra[1]=a0.y; ra[2]=a0.z; ra[3]=a0.w;
            ra[4]=a1.x; ra[5]=a1.y; ra[6]=a1.z; ra[7]=a1.w;
            float rb[TN];
            if (TN == 4) {
                float4 b = *reinterpret_cast<const float4*>(&Bs[k][tx * 4]);
                rb[0]=b.x; rb[1]=b.y; rb[2]=b.z; rb[3]=b.w;
            } else {
                float2 b = *reinterpret_cast<const float2*>(&Bs[k][tx * 2]);
                rb[0]=b.x; rb[1]=b.y;
            }
            #pragma unroll
            for (int i = 0; i < 8; i++)
                #pragma unroll
                for (int j = 0; j < TN; j++)
                    acc[i][j] += ra[i] * rb[j];
        }
        __syncthreads();
    }

    // epilogue
    float bv[TN];
    #pragma unroll
    for (int j = 0; j < TN; j++) bv[j] = bias[tx * TN + j];

    #pragma unroll
    for (int i = 0; i < 8; i++) {
        int row = blockRow + ty * 8 + i;
        #pragma unroll
        for (int j = 0; j < TN; j++) acc[i][j] += bv[j];

        if (NORM) {
            float ss = 0.f;
            #pragma unroll
            for (int j = 0; j < TN; j++) ss += acc[i][j] * acc[i][j];
            #pragma unroll
            for (int o = 16; o > 0; o >>= 1) ss += __shfl_xor_sync(0xffffffffu, ss, o);
            float inv = 1.f / fmaxf(sqrtf(ss), 1e-12f);
            #pragma unroll
            for (int j = 0; j < TN; j++) {
                float v = acc[i][j] * inv;
                acc[i][j] = v > 0.f ? v : 0.f;
            }
        } else {
            #pragma unroll
            for (int j = 0; j < TN; j++) acc[i][j] = fmaxf(acc[i][j], 0.f);
        }

        if (row < N_NODES) {
            if (TN == 4) {
                *reinterpret_cast<float4*>(out + (size_t)row * DOUT + tx * 4) =
                    make_float4(acc[i][0], acc[i][1], acc[i][2], acc[i][3]);
            } else {
                *reinterpret_cast<float2*>(out + (size_t)row * DOUT + tx * 2) =
                    make_float2(acc[i][0], acc[i][1]);
            }
        }
    }
}

// ---------------- launch ----------------
extern "C" void kernel_launch(void* const* d_in, const int* in_sizes, int n_in,
                              void* d_out, int out_size)
{
    const float* x        = (const float*)d_in[0];
    const int*   edge_src = (const int*)d_in[1];
    const int*   edge_dst = (const int*)d_in[2];

    // per layer: Wp, bp, Ws, Wn, b at 3 + 5*l
    const float* Wp[3]; const float* bp[3];
    const float* Ws[3]; const float* Wn[3]; const float* bb[3];
    for (int l = 0; l < 3; l++) {
        Wp[l] = (const float*)d_in[3 + 5 * l + 0];
        bp[l] = (const float*)d_in[3 + 5 * l + 1];
        Ws[l] = (const float*)d_in[3 + 5 * l + 2];
        Wn[l] = (const float*)d_in[3 + 5 * l + 3];
        bb[l] = (const float*)d_in[3 + 5 * l + 4];
    }

    float* out = (float*)d_out;

    float* h0d; cudaGetSymbolAddress((void**)&h0d, g_h0);
    float* h1d; cudaGetSymbolAddress((void**)&h1d, g_h1);
    float* xpd; cudaGetSymbolAddress((void**)&xpd, g_xp);
    float* pld; cudaGetSymbolAddress((void**)&pld, g_pooled);

    const int TPB = 256;
    const int GEMM_BLOCKS = (N_NODES + 63) / 64;          // 782
    const int EDGE_BLOCKS = (N_EDGES + TPB - 1) / TPB;    // 3125
    const int NODE_BLOCKS = (N_NODES + TPB - 1) / TPB;
    const int POOL_BLOCKS = (N_NODES * 32 + TPB - 1) / TPB;

    // ---- CSR build (once; reused by all 3 layers) ----
    zero_cursor_kernel<<<NODE_BLOCKS, TPB>>>();
    count_deg_kernel<<<EDGE_BLOCKS, TPB>>>(edge_dst);
    scan_kernel<<<1, 1024>>>();
    scatter_kernel<<<EDGE_BLOCKS, TPB>>>(edge_src, edge_dst);

    const float* hin[3]  = { x,   h0d, h1d };
    float*       hout[3] = { h0d, h1d, out };

    for (int l = 0; l < 3; l++) {
        // xp = relu(h @ Wp + bp)
        gemm_kernel<128, 4, false, false><<<GEMM_BLOCKS, TPB>>>(
            hin[l], nullptr, Wp[l], nullptr, bp[l], xpd);

        // pooled = segment_max(xp[src], dst)
        pool_kernel<<<POOL_BLOCKS, TPB>>>();

        // h_next = l2norm_relu(h @ Ws + pooled @ Wn + b)
        if (l < 2) {
            gemm_kernel<128, 4, true, true><<<GEMM_BLOCKS, TPB>>>(
                hin[l], pld, Ws[l], Wn[l], bb[l], hout[l]);
        } else {
            gemm_kernel<64, 2, true, true><<<GEMM_BLOCKS, TPB>>>(
                hin[l], pld, Ws[l], Wn[l], bb[l], hout[l]);
        }
    }
}

// round 2
// speedup vs baseline: 1.6505x; 1.6505x over previous
#include <cuda_runtime.h>
#include <math.h>

#define N_NODES 50000
#define N_EDGES 800000
#define DIN 128

// ---------------- scratch (no cudaMalloc allowed) ----------------
__device__ float g_h0[N_NODES * DIN];       // layer-1 output
__device__ float g_h1[N_NODES * DIN];       // layer-2 output
__device__ float g_xp[N_NODES * DIN];       // relu(h @ Wp + bp)
__device__ float g_pooled[N_NODES * DIN];   // segment max
__device__ int   g_rowptr[N_NODES + 1];
__device__ int   g_cursor[N_NODES];
__device__ int   g_csr[N_EDGES];

// ---------------- CSR build ----------------
__global__ void zero_cursor_kernel() {
    int i = blockIdx.x * blockDim.x + threadIdx.x;
    if (i < N_NODES) g_cursor[i] = 0;
}

__global__ void count_deg_kernel(const int* __restrict__ dst) {
    int e = blockIdx.x * blockDim.x + threadIdx.x;
    if (e < N_EDGES) atomicAdd(&g_cursor[dst[e]], 1);
}

// thread-coarsened block scan: 1024 threads x 49 elems, one shuffle scan
__global__ void scan_kernel() {
    const int T = 1024;
    const int CH = (N_NODES + T - 1) / T;  // 49
    int tid = threadIdx.x;
    int start = tid * CH;

    int vals[CH];
    int s = 0;
    #pragma unroll
    for (int j = 0; j < CH; j++) {
        int i = start + j;
        int v = (i < N_NODES) ? g_cursor[i] : 0;
        vals[j] = v; s += v;
    }
    int lane = tid & 31, w = tid >> 5;
    int inc = s;
    #pragma unroll
    for (int off = 1; off < 32; off <<= 1) {
        int t = __shfl_up_sync(0xffffffffu, inc, off);
        if (lane >= off) inc += t;
    }
    __shared__ int wsum[32];
    if (lane == 31) wsum[w] = inc;
    __syncthreads();
    if (w == 0) {
        int x = wsum[lane];
        #pragma unroll
        for (int off = 1; off < 32; off <<= 1) {
            int t = __shfl_up_sync(0xffffffffu, x, off);
            if (lane >= off) x += t;
        }
        wsum[lane] = x;
    }
    __syncthreads();
    int excl = inc - s + (w > 0 ? wsum[w - 1] : 0);
    #pragma unroll
    for (int j = 0; j < CH; j++) {
        int i = start + j;
        if (i < N_NODES) { g_rowptr[i] = excl; g_cursor[i] = excl; excl += vals[j]; }
    }
    if (tid == T - 1) g_rowptr[N_NODES] = excl;
}

__global__ void scatter_kernel(const int* __restrict__ src, const int* __restrict__ dst) {
    int e = blockIdx.x * blockDim.x + threadIdx.x;
    if (e < N_EDGES) {
        int d = dst[e];
        int pos = atomicAdd(&g_cursor[d], 1);
        g_csr[pos] = src[e];
    }
}

// ---------------- pooling: per-node warp max over CSR neighbors ----------------
// relu output >= 0, so init 0 == segment_max (and gives 0 for deg==0, matching ref)
__global__ void pool_kernel() {
    int gwarp = (blockIdx.x * blockDim.x + threadIdx.x) >> 5;
    int lane  = threadIdx.x & 31;
    if (gwarp >= N_NODES) return;
    int s = g_rowptr[gwarp];
    int e = g_rowptr[gwarp + 1];
    float4 m = make_float4(0.f, 0.f, 0.f, 0.f);
    for (int j = s; j < e; j++) {
        int src = g_csr[j];  // broadcast load
        float4 v = *reinterpret_cast<const float4*>(g_xp + (size_t)src * DIN + lane * 4);
        m.x = fmaxf(m.x, v.x); m.y = fmaxf(m.y, v.y);
        m.z = fmaxf(m.z, v.z); m.w = fmaxf(m.w, v.w);
    }
    *reinterpret_cast<float4*>(g_pooled + (size_t)gwarp * DIN + lane * 4) = m;
}

// ---------------- tf32 tensor-core GEMM ----------------
__device__ __forceinline__ float to_tf32(float x) {
    float r;
    asm("cvt.rna.tf32.f32 %0, %1;" : "=f"(r) : "f"(x));
    return r;
}

__device__ __forceinline__ void mma_tf32(float& d0, float& d1, float& d2, float& d3,
                                         float a0, float a1, float a2, float a3,
                                         float b0, float b1) {
    asm volatile(
        "mma.sync.aligned.m16n8k8.row.col.f32.tf32.tf32.f32 "
        "{%0,%1,%2,%3}, {%4,%5,%6,%7}, {%8,%9}, {%0,%1,%2,%3};"
        : "+f"(d0), "+f"(d1), "+f"(d2), "+f"(d3)
        : "r"(__float_as_uint(a0)), "r"(__float_as_uint(a1)),
          "r"(__float_as_uint(a2)), "r"(__float_as_uint(a3)),
          "r"(__float_as_uint(b0)), "r"(__float_as_uint(b1)));
}

// BM=128 x BN=DOUT block, BK=32, 256 threads (8 warps), warp tile (BM/WR)x64.
// DUAL:  C = A1@B1 + A2@B2 (K=256).  NORM: +bias, row L2-norm, relu.  else +bias, relu.
template <int DOUT, bool DUAL, bool NORM>
__global__ void __launch_bounds__(256)
gemm_tc_kernel(const float* __restrict__ A1, const float* __restrict__ A2,
               const float* __restrict__ B1, const float* __restrict__ B2,
               const float* __restrict__ bias, float* __restrict__ out)
{
    constexpr int BM = 128, BK = 32, BN = DOUT;
    constexpr int WC = BN / 64;            // warp cols: 2 (BN=128) or 1 (BN=64)
    constexpr int WR = 8 / WC;             // warp rows: 4 or 8
    constexpr int MT = (BM / WR) / 16;     // m16 tiles per warp: 2 or 1
    constexpr int NT = 8;                  // n8 tiles per warp (64 cols)
    constexpr int KT = DUAL ? 8 : 4;       // BK tiles
    constexpr int AST = 36;                // As row stride (words): frag LDS conflict-free
    constexpr int BST = BN + 8;            // Bs row stride: 136 / 72

    __shared__ float As[BM][AST];
    __shared__ float Bs[BK][BST];
    __shared__ float ssbuf[2][BM];

    int tid = threadIdx.x;
    int lane = tid & 31, wid = tid >> 5;
    int lr = lane >> 2, lc = lane & 3;
    int wr = wid / WC, wcid = wid % WC;
    int mbase = wr * (BM / WR);
    int nbase = wcid * 64;
    int blockRow = blockIdx.x * BM;

    float acc[MT][NT][4];
    #pragma unroll
    for (int mt = 0; mt < MT; mt++)
        #pragma unroll
        for (int nt = 0; nt < NT; nt++)
            #pragma unroll
            for (int r = 0; r < 4; r++) acc[mt][nt][r] = 0.f;

    for (int kt = 0; kt < KT; kt++) {
        const float* A = (!DUAL || kt < 4) ? A1 : A2;
        const float* B = (!DUAL || kt < 4) ? B1 : B2;
        int kb = (kt & 3) * BK;

        // A tile: 128x32, 4 float4 per thread, row-major into As
        #pragma unroll
        for (int i = 0; i < 4; i++) {
            int f = tid + i * 256;
            int row = f >> 3, c4 = f & 7;
            int garow = blockRow + row;
            if (garow >= N_NODES) garow = N_NODES - 1;
            float4 av = *reinterpret_cast<const float4*>(A + (size_t)garow * DIN + kb + c4 * 4);
            float4 tv = make_float4(to_tf32(av.x), to_tf32(av.y), to_tf32(av.z), to_tf32(av.w));
            *reinterpret_cast<float4*>(&As[row][c4 * 4]) = tv;
        }
        // B tile: 32xBN
        constexpr int BF4 = (BK * BN) / (4 * 256);  // 4 or 2
        #pragma unroll
        for (int i = 0; i < BF4; i++) {
            int f = tid + i * 256;
            int brow = f / (BN / 4), bc4 = f % (BN / 4);
            float4 bv = *reinterpret_cast<const float4*>(B + (size_t)(kb + brow) * BN + bc4 * 4);
            float4 tv = make_float4(to_tf32(bv.x), to_tf32(bv.y), to_tf32(bv.z), to_tf32(bv.w));
            *reinterpret_cast<float4*>(&Bs[brow][bc4 * 4]) = tv;
        }
        __syncthreads();

        #pragma unroll
        for (int ks = 0; ks < 4; ks++) {
            int kk = ks * 8;
            float af[MT][4];
            #pragma unroll
            for (int mt = 0; mt < MT; mt++) {
                const float* p0 = &As[mbase + mt * 16 + lr][kk + lc];
                af[mt][0] = p0[0];
                af[mt][2] = p0[4];
                const float* p1 = p0 + 8 * AST;
                af[mt][1] = p1[0];
                af[mt][3] = p1[4];
            }
            float bf[NT][2];
            #pragma unroll
            for (int nt = 0; nt < NT; nt++) {
                int col = nbase + nt * 8 + lr;
                bf[nt][0] = Bs[kk + lc][col];
                bf[nt][1] = Bs[kk + lc + 4][col];
            }
            #pragma unroll
            for (int mt = 0; mt < MT; mt++)
                #pragma unroll
                for (int nt = 0; nt < NT; nt++)
                    mma_tf32(acc[mt][nt][0], acc[mt][nt][1], acc[mt][nt][2], acc[mt][nt][3],
                             af[mt][0], af[mt][1], af[mt][2], af[mt][3],
                             bf[nt][0], bf[nt][1]);
        }
        __syncthreads();
    }

    // ---- epilogue ----
    // bias add
    #pragma unroll
    for (int nt = 0; nt < NT; nt++) {
        int col = nbase + nt * 8 + 2 * lc;
        float2 bv = *reinterpret_cast<const float2*>(bias + col);
        #pragma unroll
        for (int mt = 0; mt < MT; mt++) {
            acc[mt][nt][0] += bv.x; acc[mt][nt][1] += bv.y;
            acc[mt][nt][2] += bv.x; acc[mt][nt][3] += bv.y;
        }
    }

    float inv0[MT], inv1[MT];
    if (NORM) {
        #pragma unroll
        for (int mt = 0; mt < MT; mt++) {
            float ssA = 0.f, ssB = 0.f;
            #pragma unroll
            for (int nt = 0; nt < NT; nt++) {
                ssA += acc[mt][nt][0] * acc[mt][nt][0] + acc[mt][nt][1] * acc[mt][nt][1];
                ssB += acc[mt][nt][2] * acc[mt][nt][2] + acc[mt][nt][3] * acc[mt][nt][3];
            }
            ssA += __shfl_xor_sync(0xffffffffu, ssA, 1);
            ssA += __shfl_xor_sync(0xffffffffu, ssA, 2);
            ssB += __shfl_xor_sync(0xffffffffu, ssB, 1);
            ssB += __shfl_xor_sync(0xffffffffu, ssB, 2);
            if (WC == 2) {
                int ra = mbase + mt * 16 + lr;
                if (lc == 0) { ssbuf[wcid][ra] = ssA; ssbuf[wcid][ra + 8] = ssB; }
                inv0[mt] = ssA;  // temp, finalized after sync
                inv1[mt] = ssB;
            } else {
                inv0[mt] = 1.f / fmaxf(sqrtf(ssA), 1e-12f);
                inv1[mt] = 1.f / fmaxf(sqrtf(ssB), 1e-12f);
            }
        }
        if (WC == 2) {
            __syncthreads();
            #pragma unroll
            for (int mt = 0; mt < MT; mt++) {
                int ra = mbase + mt * 16 + lr;
                float tA = ssbuf[0][ra] + ssbuf[1][ra];
                float tB = ssbuf[0][ra + 8] + ssbuf[1][ra + 8];
                inv0[mt] = 1.f / fmaxf(sqrtf(tA), 1e-12f);
                inv1[mt] = 1.f / fmaxf(sqrtf(tB), 1e-12f);
            }
        }
    }

    #pragma unroll
    for (int mt = 0; mt < MT; mt++) {
        int ra = blockRow + mbase + mt * 16 + lr;
        int rb = ra + 8;
        #pragma unroll
        for (int nt = 0; nt < NT; nt++) {
            int col = nbase + nt * 8 + 2 * lc;
            float v0 = acc[mt][nt][0], v1 = acc[mt][nt][1];
            float v2 = acc[mt][nt][2], v3 = acc[mt][nt][3];
            if (NORM) {
                v0 *= inv0[mt]; v1 *= inv0[mt];
                v2 *= inv1[mt]; v3 *= inv1[mt];
            }
            v0 = fmaxf(v0, 0.f); v1 = fmaxf(v1, 0.f);
            v2 = fmaxf(v2, 0.f); v3 = fmaxf(v3, 0.f);
            if (ra < N_NODES)
                *reinterpret_cast<float2*>(out + (size_t)ra * DOUT + col) = make_float2(v0, v1);
            if (rb < N_NODES)
                *reinterpret_cast<float2*>(out + (size_t)rb * DOUT + col) = make_float2(v2, v3);
        }
    }
}

// ---------------- launch ----------------
extern "C" void kernel_launch(void* const* d_in, const int* in_sizes, int n_in,
                              void* d_out, int out_size)
{
    const float* x        = (const float*)d_in[0];
    const int*   edge_src = (const int*)d_in[1];
    const int*   edge_dst = (const int*)d_in[2];

    const float* Wp[3]; const float* bp[3];
    const float* Ws[3]; const float* Wn[3]; const float* bb[3];
    for (int l = 0; l < 3; l++) {
        Wp[l] = (const float*)d_in[3 + 5 * l + 0];
        bp[l] = (const float*)d_in[3 + 5 * l + 1];
        Ws[l] = (const float*)d_in[3 + 5 * l + 2];
        Wn[l] = (const float*)d_in[3 + 5 * l + 3];
        bb[l] = (const float*)d_in[3 + 5 * l + 4];
    }

    float* out = (float*)d_out;

    float* h0d; cudaGetSymbolAddress((void**)&h0d, g_h0);
    float* h1d; cudaGetSymbolAddress((void**)&h1d, g_h1);
    float* xpd; cudaGetSymbolAddress((void**)&xpd, g_xp);
    float* pld; cudaGetSymbolAddress((void**)&pld, g_pooled);

    const int TPB = 256;
    const int GEMM_BLOCKS = (N_NODES + 127) / 128;        // 391
    const int EDGE_BLOCKS = (N_EDGES + TPB - 1) / TPB;
    const int NODE_BLOCKS = (N_NODES + TPB - 1) / TPB;
    const int POOL_BLOCKS = (N_NODES * 32 + TPB - 1) / TPB;

    // ---- CSR build (once; reused by all 3 layers) ----
    zero_cursor_kernel<<<NODE_BLOCKS, TPB>>>();
    count_deg_kernel<<<EDGE_BLOCKS, TPB>>>(edge_dst);
    scan_kernel<<<1, 1024>>>();
    scatter_kernel<<<EDGE_BLOCKS, TPB>>>(edge_src, edge_dst);

    const float* hin[3]  = { x,   h0d, h1d };
    float*       hout[3] = { h0d, h1d, out };

    for (int l = 0; l < 3; l++) {
        // xp = relu(h @ Wp + bp)
        gemm_tc_kernel<128, false, false><<<GEMM_BLOCKS, TPB>>>(
            hin[l], nullptr, Wp[l], nullptr, bp[l], xpd);

        // pooled = segment_max(xp[src], dst)
        pool_kernel<<<POOL_BLOCKS, TPB>>>();

        // h_next = l2norm_relu(h @ Ws + pooled @ Wn + b)
        if (l < 2) {
            gemm_tc_kernel<128, true, true><<<GEMM_BLOCKS, TPB>>>(
                hin[l], pld, Ws[l], Wn[l], bb[l], hout[l]);
        } else {
            gemm_tc_kernel<64, true, true><<<GEMM_BLOCKS, TPB>>>(
                hin[l], pld, Ws[l], Wn[l], bb[l], hout[l]);
        }
    }
}

// round 3
// speedup vs baseline: 1.6921x; 1.0252x over previous
#include <cuda_runtime.h>
#include <cuda_fp16.h>
#include <math.h>

#define N_NODES 50000
#define N_EDGES 800000
#define DIN 128

// ---------------- scratch (no cudaMalloc allowed) ----------------
__device__ __half g_h0[N_NODES * DIN];
__device__ __half g_h1[N_NODES * DIN];
__device__ __half g_xp[N_NODES * DIN];
__device__ __half g_pooled[N_NODES * DIN];
__device__ int    g_rowptr[N_NODES + 1];
__device__ int    g_cursor[N_NODES];
__device__ int    g_csr[N_EDGES];

struct alignas(8) H4 { __half2 a, b; };

static __device__ __forceinline__ __half2 as_half2(unsigned u) {
    return *reinterpret_cast<__half2*>(&u);
}

// ---------------- CSR build ----------------
__global__ void count_deg_kernel(const int4* __restrict__ dst4) {
    int i = blockIdx.x * blockDim.x + threadIdx.x;
    if (i < N_EDGES / 4) {
        int4 d = dst4[i];
        atomicAdd(&g_cursor[d.x], 1);
        atomicAdd(&g_cursor[d.y], 1);
        atomicAdd(&g_cursor[d.z], 1);
        atomicAdd(&g_cursor[d.w], 1);
    }
}

// thread-coarsened block scan: 1024 threads x 49 elems, one shuffle scan
__global__ void scan_kernel() {
    const int T = 1024;
    const int CH = (N_NODES + T - 1) / T;  // 49
    int tid = threadIdx.x;
    int start = tid * CH;

    int vals[CH];
    int s = 0;
    #pragma unroll
    for (int j = 0; j < CH; j++) {
        int i = start + j;
        int v = (i < N_NODES) ? g_cursor[i] : 0;
        vals[j] = v; s += v;
    }
    int lane = tid & 31, w = tid >> 5;
    int inc = s;
    #pragma unroll
    for (int off = 1; off < 32; off <<= 1) {
        int t = __shfl_up_sync(0xffffffffu, inc, off);
        if (lane >= off) inc += t;
    }
    __shared__ int wsum[32];
    if (lane == 31) wsum[w] = inc;
    __syncthreads();
    if (w == 0) {
        int x = wsum[lane];
        #pragma unroll
        for (int off = 1; off < 32; off <<= 1) {
            int t = __shfl_up_sync(0xffffffffu, x, off);
            if (lane >= off) x += t;
        }
        wsum[lane] = x;
    }
    __syncthreads();
    int excl = inc - s + (w > 0 ? wsum[w - 1] : 0);
    #pragma unroll
    for (int j = 0; j < CH; j++) {
        int i = start + j;
        if (i < N_NODES) { g_rowptr[i] = excl; g_cursor[i] = excl; excl += vals[j]; }
    }
    if (tid == T - 1) g_rowptr[N_NODES] = excl;
}

__global__ void scatter_kernel(const int4* __restrict__ src4, const int4* __restrict__ dst4) {
    int i = blockIdx.x * blockDim.x + threadIdx.x;
    if (i < N_EDGES / 4) {
        int4 s = src4[i];
        int4 d = dst4[i];
        int p0 = atomicAdd(&g_cursor[d.x], 1);
        int p1 = atomicAdd(&g_cursor[d.y], 1);
        int p2 = atomicAdd(&g_cursor[d.z], 1);
        int p3 = atomicAdd(&g_cursor[d.w], 1);
        g_csr[p0] = s.x; g_csr[p1] = s.y; g_csr[p2] = s.z; g_csr[p3] = s.w;
    }
}

// ---------------- pooling: per-node warp max over CSR neighbors (fp16) --------
// relu output >= 0, so 0-init max == segment_max (and deg==0 -> 0, matching ref)
__global__ void pool_kernel() {
    int node = (blockIdx.x * blockDim.x + threadIdx.x) >> 5;
    int lane = threadIdx.x & 31;
    if (node >= N_NODES) return;
    int s = g_rowptr[node];
    int e = g_rowptr[node + 1];
    __half2 m0 = __float2half2_rn(0.f), m1 = m0;
    int j = s;
    for (; j + 4 <= e; j += 4) {
        int i0 = g_csr[j], i1 = g_csr[j + 1], i2 = g_csr[j + 2], i3 = g_csr[j + 3];
        H4 v0 = *reinterpret_cast<const H4*>(g_xp + (size_t)i0 * DIN + lane * 4);
        H4 v1 = *reinterpret_cast<const H4*>(g_xp + (size_t)i1 * DIN + lane * 4);
        H4 v2 = *reinterpret_cast<const H4*>(g_xp + (size_t)i2 * DIN + lane * 4);
        H4 v3 = *reinterpret_cast<const H4*>(g_xp + (size_t)i3 * DIN + lane * 4);
        m0 = __hmax2(m0, v0.a); m1 = __hmax2(m1, v0.b);
        m0 = __hmax2(m0, v1.a); m1 = __hmax2(m1, v1.b);
        m0 = __hmax2(m0, v2.a); m1 = __hmax2(m1, v2.b);
        m0 = __hmax2(m0, v3.a); m1 = __hmax2(m1, v3.b);
    }
    for (; j < e; j++) {
        int i0 = g_csr[j];
        H4 v = *reinterpret_cast<const H4*>(g_xp + (size_t)i0 * DIN + lane * 4);
        m0 = __hmax2(m0, v.a); m1 = __hmax2(m1, v.b);
    }
    H4 o; o.a = m0; o.b = m1;
    *reinterpret_cast<H4*>(g_pooled + (size_t)node * DIN + lane * 4) = o;
}

// ---------------- tf32 tensor-core GEMM ----------------
__device__ __forceinline__ float to_tf32(float x) {
    float r;
    asm("cvt.rna.tf32.f32 %0, %1;" : "=f"(r) : "f"(x));
    return r;
}

__device__ __forceinline__ void mma_tf32(float& d0, float& d1, float& d2, float& d3,
                                         float a0, float a1, float a2, float a3,
                                         float b0, float b1) {
    asm volatile(
        "mma.sync.aligned.m16n8k8.row.col.f32.tf32.tf32.f32 "
        "{%0,%1,%2,%3}, {%4,%5,%6,%7}, {%8,%9}, {%0,%1,%2,%3};"
        : "+f"(d0), "+f"(d1), "+f"(d2), "+f"(d3)
        : "r"(__float_as_uint(a0)), "r"(__float_as_uint(a1)),
          "r"(__float_as_uint(a2)), "r"(__float_as_uint(a3)),
          "r"(__float_as_uint(b0)), "r"(__float_as_uint(b1)));
}

// BM=128 x BN=DOUT, BK=32, 256 threads (8 warps), double-buffered smem +
// register prefetch (one sync per k-tile).
// DUAL: C = A1@B1 + A2@B2 (K=256), A2 always fp16.  A1 fp32 or fp16 (A1HALF).
// NORM: +bias, row L2-norm, relu.  else: +bias, relu.  OUTHALF: fp16 output.
template <int DOUT, bool DUAL, bool NORM, bool A1HALF, bool OUTHALF>
__global__ void __launch_bounds__(256)
gemm_tc_kernel(const void* __restrict__ A1v, const __half* __restrict__ A2,
               const float* __restrict__ B1, const float* __restrict__ B2,
               const float* __restrict__ bias, void* __restrict__ outv)
{
    constexpr int BM = 128, BK = 32, BN = DOUT;
    constexpr int WC = BN / 64;
    constexpr int WR = 8 / WC;
    constexpr int MT = (BM / WR) / 16;
    constexpr int NT = 8;
    constexpr int KT = DUAL ? 8 : 4;
    constexpr int AST = 36;        // conflict-free fragment reads
    constexpr int BST = BN + 8;
    constexpr int ASZ = BM * AST;
    constexpr int BSZ = BK * BST;
    constexpr int BF4 = (BK * BN) / (4 * 256);   // 4 (BN=128) or 2 (BN=64)

    extern __shared__ float smem[];
    float* Asb[2] = { smem, smem + ASZ };
    float* Bsb[2] = { smem + 2 * ASZ, smem + 2 * ASZ + BSZ };
    __shared__ float ssbuf[2][BM];

    const float* A1f = (const float*)A1v;
    const __half* A1h = (const __half*)A1v;

    int tid = threadIdx.x;
    int lane = tid & 31, wid = tid >> 5;
    int lr = lane >> 2, lc = lane & 3;
    int wr = wid / WC, wcid = wid % WC;
    int mbase = wr * (BM / WR);
    int nbase = wcid * 64;
    int blockRow = blockIdx.x * BM;

    float acc[MT][NT][4];
    #pragma unroll
    for (int mt = 0; mt < MT; mt++)
        #pragma unroll
        for (int nt = 0; nt < NT; nt++)
            #pragma unroll
            for (int r = 0; r < 4; r++) acc[mt][nt][r] = 0.f;

    // prefetch registers
    float4 fav[4];
    uint4  hav[2];
    float4 bvr[BF4];

    auto ldg_tile = [&](int kt) {
        int kb = (kt & 3) * BK;
        const float* B = (!DUAL || kt < 4) ? B1 : B2;
        #pragma unroll
        for (int i = 0; i < BF4; i++) {
            int f = tid + i * 256;
            int brow = f / (BN / 4), bc4 = f % (BN / 4);
            bvr[i] = *reinterpret_cast<const float4*>(B + (size_t)(kb + brow) * BN + bc4 * 4);
        }
        bool a2 = DUAL && kt >= 4;
        if (!a2 && !A1HALF) {
            #pragma unroll
            for (int i = 0; i < 4; i++) {
                int f = tid + i * 256;
                int row = f >> 3, c4 = f & 7;
                int gr = blockRow + row; if (gr >= N_NODES) gr = N_NODES - 1;
                fav[i] = *reinterpret_cast<const float4*>(A1f + (size_t)gr * DIN + kb + c4 * 4);
            }
        } else {
            const __half* Ah = a2 ? A2 : A1h;
            #pragma unroll
            for (int i = 0; i < 2; i++) {
                int f = tid + i * 256;
                int row = f >> 2, g8 = f & 3;
                int gr = blockRow + row; if (gr >= N_NODES) gr = N_NODES - 1;
                hav[i] = *reinterpret_cast<const uint4*>(Ah + (size_t)gr * DIN + kb + g8 * 8);
            }
        }
    };

    auto sts_tile = [&](int kt) {
        float* As = Asb[kt & 1];
        float* Bs = Bsb[kt & 1];
        #pragma unroll
        for (int i = 0; i < BF4; i++) {
            int f = tid + i * 256;
            int brow = f / (BN / 4), bc4 = f % (BN / 4);
            float4 t = make_float4(to_tf32(bvr[i].x), to_tf32(bvr[i].y),
                                   to_tf32(bvr[i].z), to_tf32(bvr[i].w));
            *reinterpret_cast<float4*>(Bs + brow * BST + bc4 * 4) = t;
        }
        bool a2 = DUAL && kt >= 4;
        if (!a2 && !A1HALF) {
            #pragma unroll
            for (int i = 0; i < 4; i++) {
                int f = tid + i * 256;
                int row = f >> 3, c4 = f & 7;
                float4 t = make_float4(to_tf32(fav[i].x), to_tf32(fav[i].y),
                                       to_tf32(fav[i].z), to_tf32(fav[i].w));
                *reinterpret_cast<float4*>(As + row * AST + c4 * 4) = t;
            }
        } else {
            #pragma unroll
            for (int i = 0; i < 2; i++) {
                int f = tid + i * 256;
                int row = f >> 2, g8 = f & 3;
                float2 f0 = __half22float2(as_half2(hav[i].x));
                float2 f1 = __half22float2(as_half2(hav[i].y));
                float2 f2 = __half22float2(as_half2(hav[i].z));
                float2 f3 = __half22float2(as_half2(hav[i].w));
                // fp16 -> tf32 is exact; no cvt needed
                *reinterpret_cast<float4*>(As + row * AST + g8 * 8)     = make_float4(f0.x, f0.y, f1.x, f1.y);
                *reinterpret_cast<float4*>(As + row * AST + g8 * 8 + 4) = make_float4(f2.x, f2.y, f3.x, f3.y);
            }
        }
    };

    ldg_tile(0);
    sts_tile(0);
    __syncthreads();

    for (int kt = 0; kt < KT; kt++) {
        if (kt + 1 < KT) ldg_tile(kt + 1);

        const float* As = Asb[kt & 1];
        const float* Bs = Bsb[kt & 1];
        #pragma unroll
        for (int ks = 0; ks < 4; ks++) {
            int kk = ks * 8;
            float af[MT][4];
            #pragma unroll
            for (int mt = 0; mt < MT; mt++) {
                const float* p0 = As + (mbase + mt * 16 + lr) * AST + kk + lc;
                af[mt][0] = p0[0];
                af[mt][2] = p0[4];
                const float* p1 = p0 + 8 * AST;
                af[mt][1] = p1[0];
                af[mt][3] = p1[4];
            }
            float bf[NT][2];
            #pragma unroll
            for (int nt = 0; nt < NT; nt++) {
                int col = nbase + nt * 8 + lr;
                bf[nt][0] = Bs[(kk + lc) * BST + col];
                bf[nt][1] = Bs[(kk + lc + 4) * BST + col];
            }
            #pragma unroll
            for (int mt = 0; mt < MT; mt++)
                #pragma unroll
                for (int nt = 0; nt < NT; nt++)
                    mma_tf32(acc[mt][nt][0], acc[mt][nt][1], acc[mt][nt][2], acc[mt][nt][3],
                             af[mt][0], af[mt][1], af[mt][2], af[mt][3],
                             bf[nt][0], bf[nt][1]);
        }

        if (kt + 1 < KT) sts_tile(kt + 1);
        __syncthreads();
    }

    // ---- epilogue ----
    #pragma unroll
    for (int nt = 0; nt < NT; nt++) {
        int col = nbase + nt * 8 + 2 * lc;
        float2 bv = *reinterpret_cast<const float2*>(bias + col);
        #pragma unroll
        for (int mt = 0; mt < MT; mt++) {
            acc[mt][nt][0] += bv.x; acc[mt][nt][1] += bv.y;
            acc[mt][nt][2] += bv.x; acc[mt][nt][3] += bv.y;
        }
    }

    float inv0[MT], inv1[MT];
    if (NORM) {
        #pragma unroll
        for (int mt = 0; mt < MT; mt++) {
            float ssA = 0.f, ssB = 0.f;
            #pragma unroll
            for (int nt = 0; nt < NT; nt++) {
                ssA += acc[mt][nt][0] * acc[mt][nt][0] + acc[mt][nt][1] * acc[mt][nt][1];
                ssB += acc[mt][nt][2] * acc[mt][nt][2] + acc[mt][nt][3] * acc[mt][nt][3];
            }
            ssA += __shfl_xor_sync(0xffffffffu, ssA, 1);
            ssA += __shfl_xor_sync(0xffffffffu, ssA, 2);
            ssB += __shfl_xor_sync(0xffffffffu, ssB, 1);
            ssB += __shfl_xor_sync(0xffffffffu, ssB, 2);
            if (WC == 2) {
                int ra = mbase + mt * 16 + lr;
                if (lc == 0) { ssbuf[wcid][ra] = ssA; ssbuf[wcid][ra + 8] = ssB; }
            } else {
                inv0[mt] = 1.f / fmaxf(sqrtf(ssA), 1e-12f);
                inv1[mt] = 1.f / fmaxf(sqrtf(ssB), 1e-12f);
            }
        }
        if (WC == 2) {
            __syncthreads();
            #pragma unroll
            for (int mt = 0; mt < MT; mt++) {
                int ra = mbase + mt * 16 + lr;
                float tA = ssbuf[0][ra] + ssbuf[1][ra];
                float tB = ssbuf[0][ra + 8] + ssbuf[1][ra + 8];
                inv0[mt] = 1.f / fmaxf(sqrtf(tA), 1e-12f);
                inv1[mt] = 1.f / fmaxf(sqrtf(tB), 1e-12f);
            }
        }
    }

    #pragma unroll
    for (int mt = 0; mt < MT; mt++) {
        int ra = blockRow + mbase + mt * 16 + lr;
        int rb = ra + 8;
        #pragma unroll
        for (int nt = 0; nt < NT; nt++) {
            int col = nbase + nt * 8 + 2 * lc;
            float v0 = acc[mt][nt][0], v1 = acc[mt][nt][1];
            float v2 = acc[mt][nt][2], v3 = acc[mt][nt][3];
            if (NORM) {
                v0 *= inv0[mt]; v1 *= inv0[mt];
                v2 *= inv1[mt]; v3 *= inv1[mt];
            }
            v0 = fmaxf(v0, 0.f); v1 = fmaxf(v1, 0.f);
            v2 = fmaxf(v2, 0.f); v3 = fmaxf(v3, 0.f);
            if (OUTHALF) {
                __half* out = (__half*)outv;
                if (ra < N_NODES)
                    *reinterpret_cast<__half2*>(out + (size_t)ra * DOUT + col) = __floats2half2_rn(v0, v1);
                if (rb < N_NODES)
                    *reinterpret_cast<__half2*>(out + (size_t)rb * DOUT + col) = __floats2half2_rn(v2, v3);
            } else {
                float* out = (float*)outv;
                if (ra < N_NODES)
                    *reinterpret_cast<float2*>(out + (size_t)ra * DOUT + col) = make_float2(v0, v1);
                if (rb < N_NODES)
                    *reinterpret_cast<float2*>(out + (size_t)rb * DOUT + col) = make_float2(v2, v3);
            }
        }
    }
}

// ---------------- launch ----------------
extern "C" void kernel_launch(void* const* d_in, const int* in_sizes, int n_in,
                              void* d_out, int out_size)
{
    const float* x        = (const float*)d_in[0];
    const int*   edge_src = (const int*)d_in[1];
    const int*   edge_dst = (const int*)d_in[2];

    const float* Wp[3]; const float* bp[3];
    const float* Ws[3]; const float* Wn[3]; const float* bb[3];
    for (int l = 0; l < 3; l++) {
        Wp[l] = (const float*)d_in[3 + 5 * l + 0];
        bp[l] = (const float*)d_in[3 + 5 * l + 1];
        Ws[l] = (const float*)d_in[3 + 5 * l + 2];
        Wn[l] = (const float*)d_in[3 + 5 * l + 3];
        bb[l] = (const float*)d_in[3 + 5 * l + 4];
    }

    float* out = (float*)d_out;

    __half* h0d; cudaGetSymbolAddress((void**)&h0d, g_h0);
    __half* h1d; cudaGetSymbolAddress((void**)&h1d, g_h1);
    __half* xpd; cudaGetSymbolAddress((void**)&xpd, g_xp);
    __half* pld; cudaGetSymbolAddress((void**)&pld, g_pooled);
    int* curd;  cudaGetSymbolAddress((void**)&curd, g_cursor);

    const int TPB = 256;
    const int GEMM_BLOCKS = (N_NODES + 127) / 128;              // 391
    const int EDGE4_BLOCKS = (N_EDGES / 4 + TPB - 1) / TPB;     // 782
    const int POOL_BLOCKS = (N_NODES * 32 + TPB - 1) / TPB;

    constexpr int SMEM_BN128 = (2 * 128 * 36 + 2 * 32 * 136) * 4;  // 71680
    constexpr int SMEM_BN64  = (2 * 128 * 36 + 2 * 32 * 72) * 4;   // 55296

    static bool attr_done = false;
    if (!attr_done) {
        cudaFuncSetAttribute((const void*)gemm_tc_kernel<128, false, false, false, true>,
                             cudaFuncAttributeMaxDynamicSharedMemorySize, SMEM_BN128);
        cudaFuncSetAttribute((const void*)gemm_tc_kernel<128, true, true, false, true>,
                             cudaFuncAttributeMaxDynamicSharedMemorySize, SMEM_BN128);
        cudaFuncSetAttribute((const void*)gemm_tc_kernel<128, false, false, true, true>,
                             cudaFuncAttributeMaxDynamicSharedMemorySize, SMEM_BN128);
        cudaFuncSetAttribute((const void*)gemm_tc_kernel<128, true, true, true, true>,
                             cudaFuncAttributeMaxDynamicSharedMemorySize, SMEM_BN128);
        cudaFuncSetAttribute((const void*)gemm_tc_kernel<64, true, true, true, false>,
                             cudaFuncAttributeMaxDynamicSharedMemorySize, SMEM_BN64);
        attr_done = true;
    }

    // ---- CSR build (once; reused by all 3 layers) ----
    cudaMemsetAsync(curd, 0, N_NODES * sizeof(int));
    count_deg_kernel<<<EDGE4_BLOCKS, TPB>>>((const int4*)edge_dst);
    scan_kernel<<<1, 1024>>>();
    scatter_kernel<<<EDGE4_BLOCKS, TPB>>>((const int4*)edge_src, (const int4*)edge_dst);

    // ---- layer 1 (A1 = x, fp32) ----
    gemm_tc_kernel<128, false, false, false, true><<<GEMM_BLOCKS, TPB, SMEM_BN128>>>(
        x, nullptr, Wp[0], nullptr, bp[0], xpd);
    pool_kernel<<<POOL_BLOCKS, TPB>>>();
    gemm_tc_kernel<128, true, true, false, true><<<GEMM_BLOCKS, TPB, SMEM_BN128>>>(
        x, pld, Ws[0], Wn[0], bb[0], h0d);

    // ---- layer 2 (A1 = h0, fp16) ----
    gemm_tc_kernel<128, false, false, true, true><<<GEMM_BLOCKS, TPB, SMEM_BN128>>>(
        h0d, nullptr, Wp[1], nullptr, bp[1], xpd);
    pool_kernel<<<POOL_BLOCKS, TPB>>>();
    gemm_tc_kernel<128, true, true, true, true><<<GEMM_BLOCKS, TPB, SMEM_BN128>>>(
        h0d, pld, Ws[1], Wn[1], bb[1], h1d);

    // ---- layer 3 (A1 = h1, fp16; out = d_out fp32) ----
    gemm_tc_kernel<128, false, false, true, true><<<GEMM_BLOCKS, TPB, SMEM_BN128>>>(
        h1d, nullptr, Wp[2], nullptr, bp[2], xpd);
    pool_kernel<<<POOL_BLOCKS, TPB>>>();
    gemm_tc_kernel<64, true, true, true, false><<<GEMM_BLOCKS, TPB, SMEM_BN64>>>(
        h1d, pld, Ws[2], Wn[2], bb[2], out);
}